// round 1
// baseline (speedup 1.0000x reference)
#include <cuda_runtime.h>
#include <math.h>

#define DD 64
#define KF 16
#define PP 2
#define NTASK (DD*PP)
#define NB1 296   // 2 full waves on 148 SMs

__device__ float g_Gpart[NB1 * DD * DD];
__device__ float g_G[DD * DD];
__device__ float g_task[NTASK];

// ---------------------------------------------------------------------------
// Kernel 1: partial SYRK  Gpart[b] = X_b^T X_b  (upper-triangle 4x4 blocks)
// 256 threads, 136 active compute threads own a 4x4 tile of the 64x64 output,
// restricted to ti <= tj 4x4 blocks (symmetry halves FMA work).
// ---------------------------------------------------------------------------
__global__ __launch_bounds__(256) void k_syrk(const float* __restrict__ x,
                                              int n, int rows_per) {
    __shared__ float xs[16 * 64];
    int tid = threadIdx.x;
    int ti = 0, tj = 0;
    bool active = (tid < 136);
    if (active) {
        int pr = tid, row = 0;
        while (pr >= 16 - row) { pr -= 16 - row; row++; }
        ti = row; tj = row + pr;
    }
    float acc[16];
#pragma unroll
    for (int i = 0; i < 16; i++) acc[i] = 0.0f;

    long row0 = (long)blockIdx.x * rows_per;
    for (int t0 = 0; t0 < rows_per; t0 += 16) {
        long rr0 = row0 + t0 + (tid >> 4);
        float4 v = make_float4(0.f, 0.f, 0.f, 0.f);
        if (rr0 < n) v = ((const float4*)x)[rr0 * 16 + (tid & 15)];
        ((float4*)xs)[tid] = v;
        __syncthreads();
        if (active) {
#pragma unroll
            for (int rr = 0; rr < 16; rr++) {
                float4 a = *(const float4*)&xs[rr * 64 + ti * 4];
                float4 b = *(const float4*)&xs[rr * 64 + tj * 4];
                acc[0]  += a.x * b.x;  acc[1]  += a.x * b.y;
                acc[2]  += a.x * b.z;  acc[3]  += a.x * b.w;
                acc[4]  += a.y * b.x;  acc[5]  += a.y * b.y;
                acc[6]  += a.y * b.z;  acc[7]  += a.y * b.w;
                acc[8]  += a.z * b.x;  acc[9]  += a.z * b.y;
                acc[10] += a.z * b.z;  acc[11] += a.z * b.w;
                acc[12] += a.w * b.x;  acc[13] += a.w * b.y;
                acc[14] += a.w * b.z;  acc[15] += a.w * b.w;
            }
        }
        __syncthreads();
    }
    if (active) {
        float* dst = g_Gpart + (size_t)blockIdx.x * (DD * DD);
#pragma unroll
        for (int ii = 0; ii < 4; ii++)
#pragma unroll
            for (int jj = 0; jj < 4; jj++)
                dst[(ti * 4 + ii) * 64 + tj * 4 + jj] = acc[ii * 4 + jj];
    }
}

// ---------------------------------------------------------------------------
// Kernel 2: reduce partials into full symmetric G (mirror lower from upper).
// ---------------------------------------------------------------------------
__global__ __launch_bounds__(256) void k_redG() {
    int e = blockIdx.x * blockDim.x + threadIdx.x;   // 4096 entries
    int i = e >> 6, j = e & 63;
    int src = (i <= j) ? e : (j * 64 + i);
    float s = 0.0f;
    for (int b = 0; b < NB1; b++) s += g_Gpart[(size_t)b * (DD * DD) + src];
    g_G[e] = s;
}

// ---------------------------------------------------------------------------
// Kernel 3: one block per (a,p) task. Woodbury: only a 16x16 inverse needed.
//   C   = Wr^T Wr + 0.1 I            (16x16)
//   v_j = 0.1 (1 + w_j^T C^-1 w_j)
//   q_j = Gp[j,j] - 2 b_j.u_j + b_j^T H b_j,  b_j = C^-1 w_j,
//   u_j = Wr^T Gp[m:,j],  H = Wr^T Gp_rr Wr   (16x16)
// ---------------------------------------------------------------------------
__global__ __launch_bounds__(128) void k_tasks(const float* __restrict__ W,
                                               const int* __restrict__ perms,
                                               int n) {
    const int t = blockIdx.x;
    const int a = t >> 1;               // P = 2
    const int m = a + 1;
    const int r = DD - m;
    const int tid = threadIdx.x;
    const int nt = 128;

    __shared__ float Gp[DD * DD];       // 16 KB
    __shared__ float Wp[DD * KF];       // 4 KB
    __shared__ float C[KF * KF];
    __shared__ float T[63 * KF];
    __shared__ float H[KF * KF];
    __shared__ float fcol[KF];
    __shared__ float tbuf[DD];
    __shared__ int pm[DD];

    if (tid < DD) pm[tid] = perms[t * DD + tid];
    __syncthreads();

    for (int idx = tid; idx < DD * KF; idx += nt) {
        int i = idx >> 4, k = idx & 15;
        Wp[idx] = W[pm[i] * KF + k];
    }
    for (int idx = tid; idx < DD * DD; idx += nt) {
        int i = idx >> 6, j = idx & 63;
        Gp[idx] = g_G[pm[i] * DD + pm[j]];
    }
    __syncthreads();

    // C = Wr^T Wr + 0.1 I
    for (int idx = tid; idx < KF * KF; idx += nt) {
        int s = idx >> 4, u = idx & 15;
        float acc = (s == u) ? 0.1f : 0.0f;
        for (int i = 0; i < r; i++)
            acc += Wp[(m + i) * KF + s] * Wp[(m + i) * KF + u];
        C[idx] = acc;
    }
    __syncthreads();

    // In-place Gauss-Jordan inverse of C (SPD, no pivoting needed)
    for (int k = 0; k < KF; k++) {
        if (tid < KF) fcol[tid] = C[tid * KF + k];
        __syncthreads();
        float ip = 1.0f / fcol[k];
        if (tid < KF) C[k * KF + tid] = (tid == k) ? ip : C[k * KF + tid] * ip;
        __syncthreads();
        for (int idx = tid; idx < KF * KF; idx += nt) {
            int i = idx >> 4, j = idx & 15;
            if (i != k) {
                float f = fcol[i];
                C[idx] = (j == k) ? (-f * ip) : (C[idx] - f * C[k * KF + j]);
            }
        }
        __syncthreads();
    }

    // T = Gp_rr * Wr   (r x 16)
    for (int idx = tid; idx < r * KF; idx += nt) {
        int i = idx >> 4, s = idx & 15;
        float acc = 0.0f;
        for (int l = 0; l < r; l++)
            acc += Gp[(m + i) * DD + m + l] * Wp[(m + l) * KF + s];
        T[idx] = acc;
    }
    __syncthreads();

    // H = Wr^T * T   (16 x 16)
    for (int idx = tid; idx < KF * KF; idx += nt) {
        int s = idx >> 4, u = idx & 15;
        float acc = 0.0f;
        for (int i = 0; i < r; i++)
            acc += Wp[(m + i) * KF + s] * T[i * KF + u];
        H[idx] = acc;
    }
    __syncthreads();

    // Per-column j terms
    if (tid < m) {
        int j = tid;
        float w[KF], b[KF], u[KF];
#pragma unroll
        for (int s = 0; s < KF; s++) w[s] = Wp[j * KF + s];
#pragma unroll
        for (int s = 0; s < KF; s++) {
            float acc = 0.0f;
#pragma unroll
            for (int t2 = 0; t2 < KF; t2++) acc += C[s * KF + t2] * w[t2];
            b[s] = acc;
        }
        float wb = 0.0f;
#pragma unroll
        for (int s = 0; s < KF; s++) wb += w[s] * b[s];
        float v = 0.1f * (1.0f + wb);

#pragma unroll
        for (int s = 0; s < KF; s++) u[s] = 0.0f;
        for (int i = 0; i < r; i++) {
            float g = Gp[(m + i) * DD + j];
#pragma unroll
            for (int s = 0; s < KF; s++) u[s] += Wp[(m + i) * KF + s] * g;
        }
        float bu = 0.0f;
#pragma unroll
        for (int s = 0; s < KF; s++) bu += b[s] * u[s];

        float bHb = 0.0f;
#pragma unroll
        for (int s = 0; s < KF; s++) {
            float acc = 0.0f;
#pragma unroll
            for (int t2 = 0; t2 < KF; t2++) acc += H[s * KF + t2] * b[t2];
            bHb += b[s] * acc;
        }
        float q = Gp[j * DD + j] - 2.0f * bu + bHb;

        const float LOG2PI = 1.8378770664093453f;
        float term = -0.5f * logf(v) - 0.5f * LOG2PI
                     - 0.5f * q / (v * (float)n);
        tbuf[j] = term;
    }
    __syncthreads();

    if (tid == 0) {
        float s = 0.0f;
        for (int j = 0; j < m; j++) s += tbuf[j];
        g_task[t] = s / (float)(PP * m);
    }
}

// ---------------------------------------------------------------------------
// Kernel 4: deterministic final reduction of 128 task values, negate.
// ---------------------------------------------------------------------------
__global__ __launch_bounds__(NTASK) void k_final(float* out) {
    __shared__ float s[NTASK];
    s[threadIdx.x] = g_task[threadIdx.x];
    __syncthreads();
    for (int ofs = NTASK / 2; ofs > 0; ofs >>= 1) {
        if (threadIdx.x < ofs) s[threadIdx.x] += s[threadIdx.x + ofs];
        __syncthreads();
    }
    if (threadIdx.x == 0) out[0] = -s[0];
}

// ---------------------------------------------------------------------------
extern "C" void kernel_launch(void* const* d_in, const int* in_sizes, int n_in,
                              void* d_out, int out_size) {
    const float* x = nullptr;
    const float* W = nullptr;
    const int* perms = nullptr;
    int nx = 0;
    for (int i = 0; i < n_in; i++) {
        if (in_sizes[i] == DD * KF)            W = (const float*)d_in[i];
        else if (in_sizes[i] == DD * PP * DD)  perms = (const int*)d_in[i];
        else { x = (const float*)d_in[i]; nx = in_sizes[i]; }
    }
    int n = nx / DD;
    int rows_per = ((n + NB1 - 1) / NB1 + 15) & ~15;

    k_syrk<<<NB1, 256>>>(x, n, rows_per);
    k_redG<<<(DD * DD) / 256, 256>>>();
    k_tasks<<<NTASK, 128>>>(W, perms, n);
    k_final<<<1, NTASK>>>((float*)d_out);
}

// round 2
// speedup vs baseline: 1.4690x; 1.4690x over previous
#include <cuda_runtime.h>
#include <math.h>

#define DD 64
#define KF 16
#define PP 2
#define NTASK (DD*PP)
#define NBLK 296            // SYRK blocks (2 per SM)
#define NPART (2*NBLK)      // one partial per (block, half)

__device__ __align__(16) float g_Gpart[NPART * DD * DD];
__device__ __align__(16) float g_G[DD * DD];
__device__ float g_task[NTASK];
__device__ int   g_ctr;     // zero-initialized; reset by last block each run

// packed f32x2 helpers
__device__ __forceinline__ void fma2(unsigned long long& d,
                                     unsigned long long a,
                                     unsigned long long b) {
    asm("fma.rn.f32x2 %0, %1, %2, %0;" : "+l"(d) : "l"(a), "l"(b));
}
__device__ __forceinline__ unsigned long long pack2(float v) {
    unsigned long long r;
    asm("mov.b64 %0, {%1, %1};" : "=l"(r) : "f"(v));
    return r;
}

// ---------------------------------------------------------------------------
// Kernel 1: partial SYRK  Gpart = X_b^T X_b, upper-triangle 4x8 tiles,
// packed f32x2 FMA. 192 threads = 2 halves x 96 (72 active compute each).
// ---------------------------------------------------------------------------
__global__ __launch_bounds__(192) void k_syrk(const float* __restrict__ x,
                                              int n, int rows_per) {
    __shared__ __align__(32) float xs[32 * 64];   // 8 KB
    const int tid  = threadIdx.x;
    const int half = tid / 96;
    const int t2   = tid % 96;
    const bool active = (t2 < 72);

    int ti = 0, tj = 0;
    if (active) {
        int pr = t2;
        while (pr >= 8 - (ti >> 1)) { pr -= 8 - (ti >> 1); ti++; }
        tj = (ti >> 1) + pr;
    }

    unsigned long long acc[16];   // [ii][jp] : 4 rows x 4 f32x2 (8 cols)
#pragma unroll
    for (int i = 0; i < 16; i++) acc[i] = 0ull;

    const int row0 = blockIdx.x * rows_per;
    for (int t0 = 0; t0 < rows_per; t0 += 32) {
        // load 32x64 floats = 512 float4 with 192 threads
        for (int idx = tid; idx < 512; idx += 192) {
            int rr = idx >> 4, c4 = idx & 15;
            int grow = row0 + t0 + rr;
            float4 v = make_float4(0.f, 0.f, 0.f, 0.f);
            if (grow < n) v = ((const float4*)x)[grow * 16 + c4];
            ((float4*)xs)[idx] = v;
        }
        __syncthreads();
        if (active) {
            const float* base = xs + half * (16 * 64);
#pragma unroll
            for (int rr = 0; rr < 16; rr++) {
                float4 a = *(const float4*)(base + rr * 64 + ti * 4);
                ulonglong2 b0 = *(const ulonglong2*)(base + rr * 64 + tj * 8);
                ulonglong2 b1 = *(const ulonglong2*)(base + rr * 64 + tj * 8 + 4);
                unsigned long long ax = pack2(a.x), ay = pack2(a.y);
                unsigned long long az = pack2(a.z), aw = pack2(a.w);
                fma2(acc[0],  ax, b0.x); fma2(acc[1],  ax, b0.y);
                fma2(acc[2],  ax, b1.x); fma2(acc[3],  ax, b1.y);
                fma2(acc[4],  ay, b0.x); fma2(acc[5],  ay, b0.y);
                fma2(acc[6],  ay, b1.x); fma2(acc[7],  ay, b1.y);
                fma2(acc[8],  az, b0.x); fma2(acc[9],  az, b0.y);
                fma2(acc[10], az, b1.x); fma2(acc[11], az, b1.y);
                fma2(acc[12], aw, b0.x); fma2(acc[13], aw, b0.y);
                fma2(acc[14], aw, b1.x); fma2(acc[15], aw, b1.y);
            }
        }
        __syncthreads();
    }

    if (active) {
        float* dst = g_Gpart + (size_t)(blockIdx.x * 2 + half) * (DD * DD)
                   + (ti * 4) * DD + tj * 8;
#pragma unroll
        for (int ii = 0; ii < 4; ii++) {
            unsigned long long a0 = acc[ii * 4 + 0], a1 = acc[ii * 4 + 1];
            unsigned long long a2 = acc[ii * 4 + 2], a3 = acc[ii * 4 + 3];
            float4 lo, hi;
            lo.x = __uint_as_float((unsigned)a0); lo.y = __uint_as_float((unsigned)(a0 >> 32));
            lo.z = __uint_as_float((unsigned)a1); lo.w = __uint_as_float((unsigned)(a1 >> 32));
            hi.x = __uint_as_float((unsigned)a2); hi.y = __uint_as_float((unsigned)(a2 >> 32));
            hi.z = __uint_as_float((unsigned)a3); hi.w = __uint_as_float((unsigned)(a3 >> 32));
            ((float4*)(dst + ii * DD))[0] = lo;
            ((float4*)(dst + ii * DD))[1] = hi;
        }
    }
}

// ---------------------------------------------------------------------------
// Kernel 2: reduce partials into full symmetric G. 128 blocks x 256 threads,
// each block owns 32 entries; 8-way split over NPART partials + smem tree.
// ---------------------------------------------------------------------------
__global__ __launch_bounds__(256) void k_redG() {
    const int lane = threadIdx.x & 31;
    const int g    = threadIdx.x >> 5;         // 0..7
    const int e    = blockIdx.x * 32 + lane;   // 0..4095
    const int i = e >> 6, j = e & 63;
    const int src = (i <= j) ? e : (j * 64 + i);

    const int per = NPART / 8;                 // 74
    float s = 0.0f;
#pragma unroll 2
    for (int k = 0; k < per; k++)
        s += g_Gpart[(size_t)(g * per + k) * (DD * DD) + src];

    __shared__ float red[256];
    red[threadIdx.x] = s;
    __syncthreads();
    for (int ofs = 128; ofs >= 32; ofs >>= 1) {
        if (threadIdx.x < ofs) red[threadIdx.x] += red[threadIdx.x + ofs];
        __syncthreads();
    }
    if (threadIdx.x < 32) g_G[e] = red[threadIdx.x];
}

// ---------------------------------------------------------------------------
// Kernel 3: one block per (a,p) task, Woodbury through the K=16 factor space.
// G staged in shared (coalesced) then permuted with LDS gathers. Final
// 128-task reduction folded in via atomic counter (deterministic tree).
// ---------------------------------------------------------------------------
__global__ __launch_bounds__(128) void k_tasks(const float* __restrict__ W,
                                               const int* __restrict__ perms,
                                               int n, float* __restrict__ out) {
    const int t   = blockIdx.x;
    const int m   = (t >> 1) + 1;     // P = 2
    const int r   = DD - m;
    const int tid = threadIdx.x;
    const int nt  = 128;

    __shared__ float Gsh[DD * DD];    // raw G; reused as T/U scratch later
    __shared__ float Gp[DD * DD];     // permuted G
    __shared__ float Wp[DD * KF];
    __shared__ float C[KF * KF];
    __shared__ float H[KF * KF];
    __shared__ float fcol[KF];
    __shared__ float tbuf[DD];
    __shared__ int   pm[DD];
    __shared__ int   isLast;

    if (tid < DD) pm[tid] = perms[t * DD + tid];
    // stage G coalesced: 1024 float4
    for (int idx = tid; idx < 1024; idx += nt)
        ((float4*)Gsh)[idx] = ((const float4*)g_G)[idx];
    __syncthreads();

    for (int idx = tid; idx < DD * KF; idx += nt) {
        int i = idx >> 4, k = idx & 15;
        Wp[idx] = W[pm[i] * KF + k];
    }
    for (int idx = tid; idx < DD * DD; idx += nt) {
        int i = idx >> 6, j = idx & 63;
        Gp[idx] = Gsh[pm[i] * DD + pm[j]];
    }
    __syncthreads();

    // Gsh is dead now — alias scratch onto it
    float* T = Gsh;                 // r x 16  (<= 1008 floats)
    float* U = Gsh + 1024;          // m x 16  (<= 1024 floats)

    // C = Wr^T Wr + 0.1 I
    for (int idx = tid; idx < KF * KF; idx += nt) {
        int s = idx >> 4, u = idx & 15;
        float acc = (s == u) ? 0.1f : 0.0f;
        for (int i = 0; i < r; i++)
            acc += Wp[(m + i) * KF + s] * Wp[(m + i) * KF + u];
        C[idx] = acc;
    }
    __syncthreads();

    // in-place Gauss-Jordan inverse (SPD)
    for (int k = 0; k < KF; k++) {
        if (tid < KF) fcol[tid] = C[tid * KF + k];
        __syncthreads();
        float ip = 1.0f / fcol[k];
        if (tid < KF) C[k * KF + tid] = (tid == k) ? ip : C[k * KF + tid] * ip;
        __syncthreads();
        for (int idx = tid; idx < KF * KF; idx += nt) {
            int i = idx >> 4, j = idx & 15;
            if (i != k) {
                float f = fcol[i];
                C[idx] = (j == k) ? (-f * ip) : (C[idx] - f * C[k * KF + j]);
            }
        }
        __syncthreads();
    }

    // T = Gp_rr * Wr   (r x 16)
    for (int idx = tid; idx < r * KF; idx += nt) {
        int i = idx >> 4, s = idx & 15;
        float acc = 0.0f;
        for (int l = 0; l < r; l++)
            acc += Gp[(m + i) * DD + m + l] * Wp[(m + l) * KF + s];
        T[idx] = acc;
    }
    // U[j][s] = sum_i Wr[i][s] * Gp[m+i][j]   (m x 16)
    for (int idx = tid; idx < m * KF; idx += nt) {
        int j = idx >> 4, s = idx & 15;
        float acc = 0.0f;
        for (int i = 0; i < r; i++)
            acc += Wp[(m + i) * KF + s] * Gp[(m + i) * DD + j];
        U[idx] = acc;
    }
    __syncthreads();

    // H = Wr^T * T   (16 x 16)
    for (int idx = tid; idx < KF * KF; idx += nt) {
        int s = idx >> 4, u = idx & 15;
        float acc = 0.0f;
        for (int i = 0; i < r; i++)
            acc += Wp[(m + i) * KF + s] * T[i * KF + u];
        H[idx] = acc;
    }
    __syncthreads();

    // per-column terms
    if (tid < m) {
        int j = tid;
        float w[KF], b[KF];
#pragma unroll
        for (int s = 0; s < KF; s++) w[s] = Wp[j * KF + s];
#pragma unroll
        for (int s = 0; s < KF; s++) {
            float acc = 0.0f;
#pragma unroll
            for (int u2 = 0; u2 < KF; u2++) acc += C[s * KF + u2] * w[u2];
            b[s] = acc;
        }
        float wb = 0.0f;
#pragma unroll
        for (int s = 0; s < KF; s++) wb += w[s] * b[s];
        float v = 0.1f * (1.0f + wb);

        float bu = 0.0f;
#pragma unroll
        for (int s = 0; s < KF; s++) bu += b[s] * U[j * KF + s];

        float bHb = 0.0f;
#pragma unroll
        for (int s = 0; s < KF; s++) {
            float acc = 0.0f;
#pragma unroll
            for (int u2 = 0; u2 < KF; u2++) acc += H[s * KF + u2] * b[u2];
            bHb += b[s] * acc;
        }
        float q = Gp[j * DD + j] - 2.0f * bu + bHb;

        const float LOG2PI = 1.8378770664093453f;
        tbuf[j] = -0.5f * logf(v) - 0.5f * LOG2PI - 0.5f * q / (v * (float)n);
    }
    __syncthreads();

    if (tid == 0) {
        float s = 0.0f;
        for (int j = 0; j < m; j++) s += tbuf[j];
        g_task[t] = s / (float)(PP * m);
    }

    // fold final reduction into the last-finishing block
    __threadfence();
    if (tid == 0) {
        int d = atomicAdd(&g_ctr, 1);
        isLast = (d == NTASK - 1);
    }
    __syncthreads();
    if (isLast) {
        float v = __ldcg(&g_task[tid]);   // nt == NTASK == 128
        tbuf[tid & 63] = 0.0f;            // reuse as 128-wide via two halves
        __syncthreads();
        __shared__ float fin[NTASK];
        fin[tid] = v;
        __syncthreads();
        for (int ofs = NTASK / 2; ofs > 0; ofs >>= 1) {
            if (tid < ofs) fin[tid] += fin[tid + ofs];
            __syncthreads();
        }
        if (tid == 0) {
            out[0] = -fin[0];
            g_ctr = 0;                    // reset for next replay
        }
    }
}

// ---------------------------------------------------------------------------
extern "C" void kernel_launch(void* const* d_in, const int* in_sizes, int n_in,
                              void* d_out, int out_size) {
    const float* x = nullptr;
    const float* W = nullptr;
    const int* perms = nullptr;
    int nx = 0;
    for (int i = 0; i < n_in; i++) {
        if (in_sizes[i] == DD * KF)            W = (const float*)d_in[i];
        else if (in_sizes[i] == DD * PP * DD)  perms = (const int*)d_in[i];
        else { x = (const float*)d_in[i]; nx = in_sizes[i]; }
    }
    int n = nx / DD;
    int rows_per = ((n + NBLK - 1) / NBLK + 31) & ~31;

    k_syrk <<<NBLK, 192>>>(x, n, rows_per);
    k_redG <<<128, 256>>>();
    k_tasks<<<NTASK, 128>>>(W, perms, n, (float*)d_out);
}